// round 15
// baseline (speedup 1.0000x reference)
#include <cuda_runtime.h>
#include <cuda_fp16.h>
#include <cstdint>
#include <cstddef>

#define B_  2
#define T_  4096
#define C_  2048
#define NH  16
#define NKV 4
#define D_  128

// Scratch (allocation-free rule: __device__ globals)
__device__ __align__(256) __half g_qh[B_ * T_ * NH * D_];    // rope'd+scaled fp16 Q
__device__ __align__(256) __half g_kh[B_ * T_ * NKV * D_];   // rope'd fp16 K
__device__ __align__(256) __half g_vh[B_ * T_ * NKV * D_];   // fp16 V [B,T,KV,D]
__device__ __align__(256) __half g_yh[B_ * T_ * NH * D_];    // fp16 attention out
__device__ __align__(256) __half g_xh [B_ * T_ * C_];        // fp16 GEMM inputs
__device__ __align__(256) __half g_wqh[NH * D_ * C_];
__device__ __align__(256) __half g_wkh[NKV * D_ * C_];
__device__ __align__(256) __half g_wvh[NKV * D_ * C_];
__device__ __align__(256) __half g_woh[C_ * C_];

// ---------------------------------------------------------------------------
// Helpers (arch-agnostic PTX only — GPU-side build targets plain sm_103,
// which rejects all sm_103a-only features like tcgen05)
// ---------------------------------------------------------------------------
__device__ __forceinline__ uint32_t smem_u32(const void* p) {
    uint32_t a;
    asm("{ .reg .u64 t; cvta.to.shared.u64 t, %1; cvt.u32.u64 %0, t; }"
        : "=r"(a) : "l"(p));
    return a;
}

__device__ __forceinline__ void cp16(uint32_t dst, const void* src) {
    asm volatile("cp.async.cg.shared.global [%0], [%1], 16;\n"
                 :: "r"(dst), "l"(src));
}
// L1-allocating variant: used for the A tile, which is shared by the two
// co-resident blocks (same blockIdx.y) -> trailing block hits L1.
__device__ __forceinline__ void cp16_ca(uint32_t dst, const void* src) {
    asm volatile("cp.async.ca.shared.global [%0], [%1], 16;\n"
                 :: "r"(dst), "l"(src));
}
#define CP_COMMIT() asm volatile("cp.async.commit_group;" ::: "memory")
#define CP_WAIT1()  asm volatile("cp.async.wait_group 1;" ::: "memory")

// fp16 mma, fp32 accumulate: D[16x8] += A[16x16] * B[16x8]
__device__ __forceinline__ void mma_f16(float* c, const uint32_t* a, const uint32_t* b) {
    asm volatile(
        "mma.sync.aligned.m16n8k16.row.col.f32.f16.f16.f32 "
        "{%0,%1,%2,%3}, {%4,%5,%6,%7}, {%8,%9}, {%0,%1,%2,%3};\n"
        : "+f"(c[0]), "+f"(c[1]), "+f"(c[2]), "+f"(c[3])
        : "r"(a[0]), "r"(a[1]), "r"(a[2]), "r"(a[3]),
          "r"(b[0]), "r"(b[1]));
}

__device__ __forceinline__ void ldsm_x4(uint32_t& r0, uint32_t& r1,
                                        uint32_t& r2, uint32_t& r3, uint32_t addr) {
    asm volatile("ldmatrix.sync.aligned.m8n8.x4.shared.b16 {%0,%1,%2,%3}, [%4];"
                 : "=r"(r0), "=r"(r1), "=r"(r2), "=r"(r3) : "r"(addr));
}

__device__ __forceinline__ void ldsm_x4_t(uint32_t& r0, uint32_t& r1,
                                          uint32_t& r2, uint32_t& r3, uint32_t addr) {
    asm volatile("ldmatrix.sync.aligned.m8n8.x4.trans.shared.b16 {%0,%1,%2,%3}, [%4];"
                 : "=r"(r0), "=r"(r1), "=r"(r2), "=r"(r3) : "r"(addr));
}

__device__ __forceinline__ uint32_t h2u(__half2 h) {
    return *reinterpret_cast<uint32_t*>(&h);
}

__device__ __forceinline__ float ex2(float x) {
    float r;
    asm("ex2.approx.f32 %0, %1;" : "=f"(r) : "f"(x));
    return r;
}

// ---------------------------------------------------------------------------
// fp16 GEMM — R12 proven config: occupancy-2, warp 64x32, 3-stage cp.async,
// single __syncthreads per k-tile. Block 128x128, 8 warps (2Mx4N),
// 256 threads, 2 blocks/SM. A-tile loads use .ca (cross-block L1 reuse).
// FUSED=1: QKV fused — bx in [0,24): 16 Q (+rope, +exp2 prescale), 4 K
//          (+rope), 4 V. FUSED=0: out-projection, fp32 destination.
// ---------------------------------------------------------------------------
#define HST 72
#define TST_B   (128 * HST * 2)           // 18432 (one A or B tile)
#define STAGE_B (2 * TST_B)               // 36864 (A+B per stage)
#define GM_SMEM (3 * STAGE_B)             // 110592 -> 2 blocks = 221KB/SM

template <int FUSED>
__global__ __launch_bounds__(256, 2) void gemm_h(
    const __half* __restrict__ A,
    const __half* __restrict__ B0, const __half* __restrict__ B1,
    const __half* __restrict__ B2,
    void* __restrict__ D0, void* __restrict__ D1, void* __restrict__ D2,
    const float* __restrict__ rope, int M, int K)
{
    extern __shared__ __align__(128) char smem[];
    const uint32_t sbase = smem_u32(smem);

    const int tid  = threadIdx.x;
    const int lane = tid & 31;
    const int warp = tid >> 5;
    const int g    = lane >> 2;
    const int tg   = lane & 3;
    const int wm   = warp & 1;
    const int wn   = warp >> 1;
    const int bm   = blockIdx.y << 7;
    const int bx   = blockIdx.x;

    // Per-block output selection (uniform across the block)
    const __half* Bg;
    char* Dst;
    int   Nout, coln0;
    bool  dorope;
    float osc = 1.0f;                     // epilogue output scale (Q only)
    if (FUSED) {
        if (bx < 16)      { coln0 = bx << 7;        Bg = B0 + (size_t)coln0 * K; Dst = (char*)D0; Nout = 2048; dorope = true;
                            osc = 0.1275174325f; }  // log2(e)/sqrt(128)
        else if (bx < 20) { coln0 = (bx - 16) << 7; Bg = B1 + (size_t)coln0 * K; Dst = (char*)D1; Nout = 512;  dorope = true;  }
        else              { coln0 = (bx - 20) << 7; Bg = B2 + (size_t)coln0 * K; Dst = (char*)D2; Nout = 512;  dorope = false; }
    } else {
        coln0 = bx << 7;
        Bg = B0 + (size_t)coln0 * K;
        Dst = (char*)D0; Nout = 2048; dorope = false;
    }

    const int arow = tid >> 3;          // 0..31
    const int aseg = tid & 7;           // 16B segs (8 per 128B row)

    // ldmatrix lane offsets (byte units)
    const uint32_t a_lrow = (lane & 7) + (((lane >> 3) & 1) << 3);
    const uint32_t a_kofb = (lane >> 4) << 4;
    const uint32_t b_lrow = (lane & 7) + ((lane >> 4) << 3);
    const uint32_t b_kofb = ((lane >> 3) & 1) << 4;

    float acc[4][4][4];
#pragma unroll
    for (int i = 0; i < 4; i++)
#pragma unroll
        for (int j = 0; j < 4; j++)
#pragma unroll
            for (int e = 0; e < 4; e++) acc[i][j][e] = 0.f;

    const __half* Ag = A + (size_t)bm * K;

    auto load_stage = [&](int sp, int kt) {
        const __half* As = Ag + (kt << 6);
        const __half* Bs = Bg + (kt << 6);
        const uint32_t ab = sbase + sp * STAGE_B;
        const uint32_t bb = ab + TST_B;
#pragma unroll
        for (int i = 0; i < 4; i++) {
            int row = arow + (i << 5);
            cp16_ca(ab + row * (HST * 2) + (aseg << 4), As + (size_t)row * K + (aseg << 3));
        }
#pragma unroll
        for (int i = 0; i < 4; i++) {
            int row = arow + (i << 5);
            cp16(bb + row * (HST * 2) + (aseg << 4), Bs + (size_t)row * K + (aseg << 3));
        }
    };

    const int nkt = K >> 6;   // 32 for K=2048
    load_stage(0, 0); CP_COMMIT();
    load_stage(1, 1); CP_COMMIT();

    int s = 0, sw = 2;        // rotating stage indices: compute s, write sw
    for (int kt = 0; kt < nkt; kt++) {
        CP_WAIT1();              // tile kt resident (only kt+1's group pends)
        __syncthreads();         // publishes kt; frees stage (kt-1)%3
        if (kt + 2 < nkt) load_stage(sw, kt + 2);
        CP_COMMIT();             // exactly one commit per iteration

        const uint32_t Asm = sbase + s * STAGE_B;
        const uint32_t Bsm = Asm + TST_B;

#pragma unroll
        for (int ks = 0; ks < 4; ks++) {
            uint32_t af[4][4];
            uint32_t bf[4][2];
#pragma unroll
            for (int mt = 0; mt < 4; mt++) {
                const uint32_t addr = Asm +
                    ((wm << 6) + (mt << 4) + a_lrow) * (HST * 2) + (ks << 5) + a_kofb;
                ldsm_x4(af[mt][0], af[mt][1], af[mt][2], af[mt][3], addr);
            }
#pragma unroll
            for (int ntp = 0; ntp < 2; ntp++) {
                const uint32_t addr = Bsm +
                    ((wn << 5) + (ntp << 4) + b_lrow) * (HST * 2) + (ks << 5) + b_kofb;
                ldsm_x4(bf[2 * ntp][0], bf[2 * ntp][1],
                        bf[2 * ntp + 1][0], bf[2 * ntp + 1][1], addr);
            }
#pragma unroll
            for (int mt = 0; mt < 4; mt++)
#pragma unroll
                for (int nt = 0; nt < 4; nt++)
                    mma_f16(acc[mt][nt], af[mt], bf[nt]);
        }
        s  = (s  == 2) ? 0 : s  + 1;
        sw = (sw == 2) ? 0 : sw + 1;
    }

#pragma unroll
    for (int mt = 0; mt < 4; mt++) {
#pragma unroll
        for (int nt = 0; nt < 4; nt++) {
            float v0 = acc[mt][nt][0], v1 = acc[mt][nt][1];
            float v2 = acc[mt][nt][2], v3 = acc[mt][nt][3];
            const int row = bm + (wm << 6) + (mt << 4) + g;
            const int col = coln0 + (wn << 5) + (nt << 3) + (tg << 1);
            if (FUSED && dorope) {
                const int t = row & (T_ - 1);
                const int d = col & 127;
                float2 cs0 = *(const float2*)(rope + (size_t)t * 128 + d);
                float2 cs8 = *(const float2*)(rope + (size_t)(t + 8) * 128 + d);
                float o0 = (v0 * cs0.x - v1 * cs0.y) * osc;
                float o1 = (v0 * cs0.y + v1 * cs0.x) * osc;
                float o2 = (v2 * cs8.x - v3 * cs8.y) * osc;
                float o3 = (v2 * cs8.y + v3 * cs8.x) * osc;
                v0 = o0; v1 = o1; v2 = o2; v3 = o3;
            }
            if (FUSED) {
                __half* C = (__half*)Dst;
                *(__half2*)(C + (size_t)row * Nout + col) = __floats2half2_rn(v0, v1);
                *(__half2*)(C + (size_t)(row + 8) * Nout + col) = __floats2half2_rn(v2, v3);
            } else {
                float* C = (float*)Dst;
                *(float2*)(C + (size_t)row * Nout + col) = make_float2(v0, v1);
                *(float2*)(C + (size_t)(row + 8) * Nout + col) = make_float2(v2, v3);
            }
        }
    }
}

// ---------------------------------------------------------------------------
// All fp32->fp16 conversions (x + 4 weight matrices) in ONE launch.
// ---------------------------------------------------------------------------
__global__ void cvt_all(__half* dx, __half* dq, __half* dk, __half* dv, __half* dw,
                        const float* sx, const float* sq, const float* sk,
                        const float* sv, const float* sw)
{
    const int n_x  = (B_ * T_ * C_) / 4;    // 4194304
    const int n_q  = (NH  * D_ * C_) / 4;   // 1048576
    const int n_kv = (NKV * D_ * C_) / 4;   // 262144
    const int n_o  = (C_ * C_) / 4;         // 1048576
    int i = blockIdx.x * blockDim.x + threadIdx.x;
    const float* src; __half* dst;
    if (i < n_x)                         { src = sx; dst = dx; }
    else if (i < n_x + n_q)              { src = sq; dst = dq; i -= n_x; }
    else if (i < n_x + n_q + n_kv)       { src = sk; dst = dk; i -= n_x + n_q; }
    else if (i < n_x + n_q + 2 * n_kv)   { src = sv; dst = dv; i -= n_x + n_q + n_kv; }
    else if (i < n_x + n_q + 2 * n_kv + n_o) { src = sw; dst = dw; i -= n_x + n_q + 2 * n_kv; }
    else return;
    float4 v = ((const float4*)src)[i];
    __half2* d = (__half2*)dst + 2 * i;
    d[0] = __floats2half2_rn(v.x, v.y);
    d[1] = __floats2half2_rn(v.z, v.w);
}

// ---------------------------------------------------------------------------
// fp16 tensor-core sliding-window attention (window 256), GQA 16:4.
// Block = 4 warps / 64 queries; 3 blocks per SM. 10 key-tiles per block.
// 3-stage cp.async, single __syncthreads per tile. Q pre-scaled by
// log2(e)/sqrt(d) -> p = ex2(s). Warp-uniform fast path for valid tiles.
// (R12 version — FADD row-sums; the mma-ones variant measured slower.)
// ---------------------------------------------------------------------------
#define AKST 136
#define AT_KB (32 * AKST * 2)            // 8704
#define AT_STAGE (2 * AT_KB)             // 17408 (K + V)
#define AT_SMEM  (3 * AT_STAGE)          // 52224

__global__ __launch_bounds__(128, 3) void attn_h(
    const __half* __restrict__ Qh, const __half* __restrict__ Kh,
    const __half* __restrict__ Vh, __half* __restrict__ Y)
{
    extern __shared__ __align__(128) char smem[];
    const uint32_t sb = smem_u32(smem);

    const int tid  = threadIdx.x;
    const int lane = tid & 31;
    const int w    = tid >> 5;          // 0..3
    const int g    = lane >> 2;
    const int tg   = lane & 3;
    const int b    = blockIdx.z;
    const int h    = blockIdx.y;
    const int c0   = blockIdx.x << 6;   // 64 queries per block
    const int kvh  = h >> 2;
    const int tr   = c0 + (w << 4) + g;

    const uint32_t qk_lbase = (lane & 7) * (AKST * 2) + ((lane >> 3) << 4);
    const uint32_t pv_lbase = ((((lane >> 3) & 1) << 3) + (lane & 7)) * (AKST * 2)
                              + ((lane >> 4) << 4);

    uint32_t qf[8][4];
    {
        const __half* q0 = Qh + ((size_t)(b * T_ + tr) * NH + h) * D_;
        const __half* q8 = q0 + (size_t)8 * NH * D_;
#pragma unroll
        for (int ks = 0; ks < 8; ks++) {
            const int c = ks * 16 + (tg << 1);
            qf[ks][0] = *(const uint32_t*)(q0 + c);
            qf[ks][1] = *(const uint32_t*)(q8 + c);
            qf[ks][2] = *(const uint32_t*)(q0 + c + 8);
            qf[ks][3] = *(const uint32_t*)(q8 + c + 8);
        }
    }

    float o[16][4];
#pragma unroll
    for (int i = 0; i < 16; i++)
#pragma unroll
        for (int e = 0; e < 4; e++) o[i][e] = 0.f;
    float l0 = 0.f, l1 = 0.f;

    auto load_tile = [&](int stage, int kbase) {
        const uint32_t kd = sb + stage * AT_STAGE;
        const uint32_t vd = kd + AT_KB;
#pragma unroll
        for (int i = 0; i < 4; i++) {
            int idx = tid + (i << 7);           // 0..511
            int row = idx >> 4, seg = idx & 15;
            const size_t gofs =
                ((size_t)(b * T_ + kbase + row) * NKV + kvh) * D_ + (seg << 3);
            cp16(kd + row * (AKST * 2) + (seg << 4), Kh + gofs);
            cp16(vd + row * (AKST * 2) + (seg << 4), Vh + gofs);
        }
    };

    const int tstart = (c0 >= 256) ? 0 : ((256 - c0) >> 5);
    load_tile(tstart % 3, c0 - 256 + (tstart << 5));
    CP_COMMIT();
    load_tile((tstart + 1) % 3, c0 - 256 + ((tstart + 1) << 5));
    CP_COMMIT();

    const int wq0 = c0 + (w << 4);

    for (int t = tstart; t < 10; t++) {
        const int kbase = c0 - 256 + (t << 5);
        CP_WAIT1();
        __syncthreads();
        if (t + 2 < 10) load_tile((t + 2) % 3, kbase + 64);
        CP_COMMIT();

        const int rel = kbase - wq0;
        const bool active = !(rel > 15 || rel < -287);
        if (active) {
            const uint32_t Ksm = sb + (t % 3) * AT_STAGE;
            const uint32_t Vsm = Ksm + AT_KB;

            float sc[4][4];
#pragma unroll
            for (int nc = 0; nc < 4; nc++)
#pragma unroll
                for (int e = 0; e < 4; e++) sc[nc][e] = 0.f;

#pragma unroll
            for (int ksp = 0; ksp < 4; ksp++) {
#pragma unroll
                for (int nc = 0; nc < 4; nc++) {
                    uint32_t r0, r1, r2, r3;
                    const uint32_t addr = Ksm + nc * (8 * AKST * 2) + (ksp << 6) + qk_lbase;
                    ldsm_x4(r0, r1, r2, r3, addr);
                    uint32_t blo[2] = { r0, r1 };
                    uint32_t bhi[2] = { r2, r3 };
                    mma_f16(sc[nc], qf[2 * ksp],     blo);
                    mma_f16(sc[nc], qf[2 * ksp + 1], bhi);
                }
            }

            uint32_t pa[2][4];
            if (rel >= -240 && rel <= -32) {
                // fully-valid tile: no masking needed (warp-uniform)
#pragma unroll
                for (int nc = 0; nc < 4; nc++) {
                    float p0 = ex2(sc[nc][0]);
                    float p1 = ex2(sc[nc][1]);
                    float p2 = ex2(sc[nc][2]);
                    float p3 = ex2(sc[nc][3]);
                    l0 += p0 + p1;
                    l1 += p2 + p3;
                    const int kc = nc >> 1;
                    const int hi = nc & 1;
                    pa[kc][2 * hi]     = h2u(__floats2half2_rn(p0, p1));
                    pa[kc][2 * hi + 1] = h2u(__floats2half2_rn(p2, p3));
                }
            } else {
#pragma unroll
                for (int nc = 0; nc < 4; nc++) {
                    const int col = kbase + nc * 8 + (tg << 1);
                    float p0 = ((unsigned)(tr - col)     < 256u) ? ex2(sc[nc][0]) : 0.f;
                    float p1 = ((unsigned)(tr - col - 1) < 256u) ? ex2(sc[nc][1]) : 0.f;
                    float p2 = ((unsigned)(tr + 8 - col) < 256u) ? ex2(sc[nc][2]) : 0.f;
                    float p3 = ((unsigned)(tr + 7 - col) < 256u) ? ex2(sc[nc][3]) : 0.f;
                    l0 += p0 + p1;
                    l1 += p2 + p3;
                    const int kc = nc >> 1;
                    const int hi = nc & 1;
                    pa[kc][2 * hi]     = h2u(__floats2half2_rn(p0, p1));
                    pa[kc][2 * hi + 1] = h2u(__floats2half2_rn(p2, p3));
                }
            }

#pragma unroll
            for (int kc = 0; kc < 2; kc++) {
#pragma unroll
                for (int ncp = 0; ncp < 8; ncp++) {
                    uint32_t r0, r1, r2, r3;
                    const uint32_t addr = Vsm + kc * (16 * AKST * 2) + (ncp << 5) + pv_lbase;
                    ldsm_x4_t(r0, r1, r2, r3, addr);
                    uint32_t blo[2] = { r0, r1 };
                    uint32_t bhi[2] = { r2, r3 };
                    mma_f16(o[2 * ncp],     pa[kc], blo);
                    mma_f16(o[2 * ncp + 1], pa[kc], bhi);
                }
            }
        }
    }

    l0 += __shfl_xor_sync(0xffffffffu, l0, 1);
    l0 += __shfl_xor_sync(0xffffffffu, l0, 2);
    l1 += __shfl_xor_sync(0xffffffffu, l1, 1);
    l1 += __shfl_xor_sync(0xffffffffu, l1, 2);
    const float rl0 = 1.0f / l0;
    const float rl1 = 1.0f / l1;

    __half2* y0 = (__half2*)(Y + ((size_t)(b * T_ + tr) * NH + h) * D_);
    __half2* y8 = (__half2*)(Y + ((size_t)(b * T_ + tr + 8) * NH + h) * D_);
#pragma unroll
    for (int nc = 0; nc < 16; nc++) {
        const int dw = nc * 4 + tg;
        y0[dw] = __floats2half2_rn(o[nc][0] * rl0, o[nc][1] * rl0);
        y8[dw] = __floats2half2_rn(o[nc][2] * rl1, o[nc][3] * rl1);
    }
}

// ---------------------------------------------------------------------------
// Launch. Inputs (metadata order): x, wq, wk, wv, wo, rope_cache. Out: fp32.
// ---------------------------------------------------------------------------
extern "C" void kernel_launch(void* const* d_in, const int* in_sizes, int n_in,
                              void* d_out, int out_size)
{
    const float* x    = (const float*)d_in[0];
    const float* wq   = (const float*)d_in[1];
    const float* wk   = (const float*)d_in[2];
    const float* wv   = (const float*)d_in[3];
    const float* wo   = (const float*)d_in[4];
    const float* rope = (const float*)d_in[5];
    float* out = (float*)d_out;

    __half *pqh, *pkh, *pvh, *pyh, *pxh, *pwqh, *pwkh, *pwvh, *pwoh;
    cudaGetSymbolAddress((void**)&pqh,  g_qh);
    cudaGetSymbolAddress((void**)&pkh,  g_kh);
    cudaGetSymbolAddress((void**)&pvh,  g_vh);
    cudaGetSymbolAddress((void**)&pyh,  g_yh);
    cudaGetSymbolAddress((void**)&pxh,  g_xh);
    cudaGetSymbolAddress((void**)&pwqh, g_wqh);
    cudaGetSymbolAddress((void**)&pwkh, g_wkh);
    cudaGetSymbolAddress((void**)&pwvh, g_wvh);
    cudaGetSymbolAddress((void**)&pwoh, g_woh);

    cudaFuncSetAttribute(gemm_h<0>, cudaFuncAttributeMaxDynamicSharedMemorySize, GM_SMEM);
    cudaFuncSetAttribute(gemm_h<1>, cudaFuncAttributeMaxDynamicSharedMemorySize, GM_SMEM);
    cudaFuncSetAttribute(attn_h,    cudaFuncAttributeMaxDynamicSharedMemorySize, AT_SMEM);

    const int M = B_ * T_;  // 8192

    // One conversion launch for x + all weights
    {
        int n4 = (B_ * T_ * C_ + NH * D_ * C_ + 2 * NKV * D_ * C_ + C_ * C_) / 4;
        cvt_all<<<(n4 + 255) / 256, 256>>>(pxh, pwqh, pwkh, pwvh, pwoh,
                                           x, wq, wk, wv, wo);
    }

    // Fused QKV projection: 24 column-blocks (16 Q + 4 K + 4 V) x 64 row-blocks
    gemm_h<1><<<dim3(24, M / 128), 256, GM_SMEM>>>(
        pxh, pwqh, pwkh, pwvh, pqh, pkh, pvh, rope, M, C_);

    // fp16 tensor-core sliding-window attention -> yh (fp16)
    attn_h<<<dim3(T_ / 64, NH, B_), 128, AT_SMEM>>>(pqh, pkh, pvh, pyh);

    // Output projection (fp16 in, fp32 out)
    gemm_h<0><<<dim3(C_ / 128, M / 128), 256, GM_SMEM>>>(
        pyh, pwoh, nullptr, nullptr, out, nullptr, nullptr, nullptr, M, C_);
}

// round 16
// speedup vs baseline: 1.0221x; 1.0221x over previous
#include <cuda_runtime.h>
#include <cuda_fp16.h>
#include <cstdint>
#include <cstddef>

#define B_  2
#define T_  4096
#define C_  2048
#define NH  16
#define NKV 4
#define D_  128

// Scratch (allocation-free rule: __device__ globals)
__device__ __align__(256) __half g_qh[B_ * T_ * NH * D_];    // rope'd+scaled fp16 Q
__device__ __align__(256) __half g_kh[B_ * T_ * NKV * D_];   // rope'd fp16 K
__device__ __align__(256) __half g_vh[B_ * T_ * NKV * D_];   // fp16 V [B,T,KV,D]
__device__ __align__(256) __half g_yh[B_ * T_ * NH * D_];    // fp16 attention out
__device__ __align__(256) __half g_xh [B_ * T_ * C_];        // fp16 GEMM inputs
__device__ __align__(256) __half g_wqh[NH * D_ * C_];
__device__ __align__(256) __half g_wkh[NKV * D_ * C_];
__device__ __align__(256) __half g_wvh[NKV * D_ * C_];
__device__ __align__(256) __half g_woh[C_ * C_];

// ---------------------------------------------------------------------------
// Helpers (arch-agnostic PTX only — GPU-side build targets plain sm_103,
// which rejects all sm_103a-only features like tcgen05)
// ---------------------------------------------------------------------------
__device__ __forceinline__ uint32_t smem_u32(const void* p) {
    uint32_t a;
    asm("{ .reg .u64 t; cvta.to.shared.u64 t, %1; cvt.u32.u64 %0, t; }"
        : "=r"(a) : "l"(p));
    return a;
}

__device__ __forceinline__ void cp16(uint32_t dst, const void* src) {
    asm volatile("cp.async.cg.shared.global [%0], [%1], 16;\n"
                 :: "r"(dst), "l"(src));
}
#define CP_COMMIT() asm volatile("cp.async.commit_group;" ::: "memory")
#define CP_WAIT1()  asm volatile("cp.async.wait_group 1;" ::: "memory")
#define CP_WAIT0()  asm volatile("cp.async.wait_group 0;" ::: "memory")

// fp16 mma, fp32 accumulate: D[16x8] += A[16x16] * B[16x8]
__device__ __forceinline__ void mma_f16(float* c, const uint32_t* a, const uint32_t* b) {
    asm volatile(
        "mma.sync.aligned.m16n8k16.row.col.f32.f16.f16.f32 "
        "{%0,%1,%2,%3}, {%4,%5,%6,%7}, {%8,%9}, {%0,%1,%2,%3};\n"
        : "+f"(c[0]), "+f"(c[1]), "+f"(c[2]), "+f"(c[3])
        : "r"(a[0]), "r"(a[1]), "r"(a[2]), "r"(a[3]),
          "r"(b[0]), "r"(b[1]));
}

__device__ __forceinline__ void ldsm_x4(uint32_t& r0, uint32_t& r1,
                                        uint32_t& r2, uint32_t& r3, uint32_t addr) {
    asm volatile("ldmatrix.sync.aligned.m8n8.x4.shared.b16 {%0,%1,%2,%3}, [%4];"
                 : "=r"(r0), "=r"(r1), "=r"(r2), "=r"(r3) : "r"(addr));
}

__device__ __forceinline__ void ldsm_x4_t(uint32_t& r0, uint32_t& r1,
                                          uint32_t& r2, uint32_t& r3, uint32_t addr) {
    asm volatile("ldmatrix.sync.aligned.m8n8.x4.trans.shared.b16 {%0,%1,%2,%3}, [%4];"
                 : "=r"(r0), "=r"(r1), "=r"(r2), "=r"(r3) : "r"(addr));
}

__device__ __forceinline__ uint32_t h2u(__half2 h) {
    return *reinterpret_cast<uint32_t*>(&h);
}

__device__ __forceinline__ float ex2(float x) {
    float r;
    asm("ex2.approx.f32 %0, %1;" : "=f"(r) : "f"(x));
    return r;
}

// ---------------------------------------------------------------------------
// fp16 GEMM — R12 exact (proven best): occupancy-2, warp 64x32, 3-stage
// cp.async (.cg only — .ca measured slower), one __syncthreads per k-tile.
// Block 128x128, 8 warps (2Mx4N), 256 threads, 2 blocks/SM.
// FUSED=1: QKV fused — bx in [0,24): 16 Q (+rope, +exp2 prescale), 4 K
//          (+rope), 4 V. FUSED=0: out-projection, fp32 destination.
// ---------------------------------------------------------------------------
#define HST 72
#define TST_B   (128 * HST * 2)           // 18432 (one A or B tile)
#define STAGE_B (2 * TST_B)               // 36864 (A+B per stage)
#define GM_SMEM (3 * STAGE_B)             // 110592 -> 2 blocks = 221KB/SM

template <int FUSED>
__global__ __launch_bounds__(256, 2) void gemm_h(
    const __half* __restrict__ A,
    const __half* __restrict__ B0, const __half* __restrict__ B1,
    const __half* __restrict__ B2,
    void* __restrict__ D0, void* __restrict__ D1, void* __restrict__ D2,
    const float* __restrict__ rope, int M, int K)
{
    extern __shared__ __align__(128) char smem[];
    const uint32_t sbase = smem_u32(smem);

    const int tid  = threadIdx.x;
    const int lane = tid & 31;
    const int warp = tid >> 5;
    const int g    = lane >> 2;
    const int tg   = lane & 3;
    const int wm   = warp & 1;
    const int wn   = warp >> 1;
    const int bm   = blockIdx.y << 7;
    const int bx   = blockIdx.x;

    // Per-block output selection (uniform across the block)
    const __half* Bg;
    char* Dst;
    int   Nout, coln0;
    bool  dorope;
    float osc = 1.0f;                     // epilogue output scale (Q only)
    if (FUSED) {
        if (bx < 16)      { coln0 = bx << 7;        Bg = B0 + (size_t)coln0 * K; Dst = (char*)D0; Nout = 2048; dorope = true;
                            osc = 0.1275174325f; }  // log2(e)/sqrt(128)
        else if (bx < 20) { coln0 = (bx - 16) << 7; Bg = B1 + (size_t)coln0 * K; Dst = (char*)D1; Nout = 512;  dorope = true;  }
        else              { coln0 = (bx - 20) << 7; Bg = B2 + (size_t)coln0 * K; Dst = (char*)D2; Nout = 512;  dorope = false; }
    } else {
        coln0 = bx << 7;
        Bg = B0 + (size_t)coln0 * K;
        Dst = (char*)D0; Nout = 2048; dorope = false;
    }

    const int arow = tid >> 3;          // 0..31
    const int aseg = tid & 7;           // 16B segs (8 per 128B row)

    // ldmatrix lane offsets (byte units)
    const uint32_t a_lrow = (lane & 7) + (((lane >> 3) & 1) << 3);
    const uint32_t a_kofb = (lane >> 4) << 4;
    const uint32_t b_lrow = (lane & 7) + ((lane >> 4) << 3);
    const uint32_t b_kofb = ((lane >> 3) & 1) << 4;

    float acc[4][4][4];
#pragma unroll
    for (int i = 0; i < 4; i++)
#pragma unroll
        for (int j = 0; j < 4; j++)
#pragma unroll
            for (int e = 0; e < 4; e++) acc[i][j][e] = 0.f;

    const __half* Ag = A + (size_t)bm * K;

    auto load_stage = [&](int sp, int kt) {
        const __half* As = Ag + (kt << 6);
        const __half* Bs = Bg + (kt << 6);
        const uint32_t ab = sbase + sp * STAGE_B;
        const uint32_t bb = ab + TST_B;
#pragma unroll
        for (int i = 0; i < 4; i++) {
            int row = arow + (i << 5);
            cp16(ab + row * (HST * 2) + (aseg << 4), As + (size_t)row * K + (aseg << 3));
        }
#pragma unroll
        for (int i = 0; i < 4; i++) {
            int row = arow + (i << 5);
            cp16(bb + row * (HST * 2) + (aseg << 4), Bs + (size_t)row * K + (aseg << 3));
        }
    };

    const int nkt = K >> 6;   // 32 for K=2048
    load_stage(0, 0); CP_COMMIT();
    load_stage(1, 1); CP_COMMIT();

    int s = 0, sw = 2;        // rotating stage indices: compute s, write sw
    for (int kt = 0; kt < nkt; kt++) {
        CP_WAIT1();              // tile kt resident (only kt+1's group pends)
        __syncthreads();         // publishes kt; frees stage (kt-1)%3
        if (kt + 2 < nkt) load_stage(sw, kt + 2);
        CP_COMMIT();             // exactly one commit per iteration

        const uint32_t Asm = sbase + s * STAGE_B;
        const uint32_t Bsm = Asm + TST_B;

#pragma unroll
        for (int ks = 0; ks < 4; ks++) {
            uint32_t af[4][4];
            uint32_t bf[4][2];
#pragma unroll
            for (int mt = 0; mt < 4; mt++) {
                const uint32_t addr = Asm +
                    ((wm << 6) + (mt << 4) + a_lrow) * (HST * 2) + (ks << 5) + a_kofb;
                ldsm_x4(af[mt][0], af[mt][1], af[mt][2], af[mt][3], addr);
            }
#pragma unroll
            for (int ntp = 0; ntp < 2; ntp++) {
                const uint32_t addr = Bsm +
                    ((wn << 5) + (ntp << 4) + b_lrow) * (HST * 2) + (ks << 5) + b_kofb;
                ldsm_x4(bf[2 * ntp][0], bf[2 * ntp][1],
                        bf[2 * ntp + 1][0], bf[2 * ntp + 1][1], addr);
            }
#pragma unroll
            for (int mt = 0; mt < 4; mt++)
#pragma unroll
                for (int nt = 0; nt < 4; nt++)
                    mma_f16(acc[mt][nt], af[mt], bf[nt]);
        }
        s  = (s  == 2) ? 0 : s  + 1;
        sw = (sw == 2) ? 0 : sw + 1;
    }

#pragma unroll
    for (int mt = 0; mt < 4; mt++) {
#pragma unroll
        for (int nt = 0; nt < 4; nt++) {
            float v0 = acc[mt][nt][0], v1 = acc[mt][nt][1];
            float v2 = acc[mt][nt][2], v3 = acc[mt][nt][3];
            const int row = bm + (wm << 6) + (mt << 4) + g;
            const int col = coln0 + (wn << 5) + (nt << 3) + (tg << 1);
            if (FUSED && dorope) {
                const int t = row & (T_ - 1);
                const int d = col & 127;
                float2 cs0 = *(const float2*)(rope + (size_t)t * 128 + d);
                float2 cs8 = *(const float2*)(rope + (size_t)(t + 8) * 128 + d);
                float o0 = (v0 * cs0.x - v1 * cs0.y) * osc;
                float o1 = (v0 * cs0.y + v1 * cs0.x) * osc;
                float o2 = (v2 * cs8.x - v3 * cs8.y) * osc;
                float o3 = (v2 * cs8.y + v3 * cs8.x) * osc;
                v0 = o0; v1 = o1; v2 = o2; v3 = o3;
            }
            if (FUSED) {
                __half* C = (__half*)Dst;
                *(__half2*)(C + (size_t)row * Nout + col) = __floats2half2_rn(v0, v1);
                *(__half2*)(C + (size_t)(row + 8) * Nout + col) = __floats2half2_rn(v2, v3);
            } else {
                float* C = (float*)Dst;
                *(float2*)(C + (size_t)row * Nout + col) = make_float2(v0, v1);
                *(float2*)(C + (size_t)(row + 8) * Nout + col) = make_float2(v2, v3);
            }
        }
    }
}

// ---------------------------------------------------------------------------
// All fp32->fp16 conversions (x + 4 weight matrices) in ONE launch.
// ---------------------------------------------------------------------------
__global__ void cvt_all(__half* dx, __half* dq, __half* dk, __half* dv, __half* dw,
                        const float* sx, const float* sq, const float* sk,
                        const float* sv, const float* sw)
{
    const int n_x  = (B_ * T_ * C_) / 4;    // 4194304
    const int n_q  = (NH  * D_ * C_) / 4;   // 1048576
    const int n_kv = (NKV * D_ * C_) / 4;   // 262144
    const int n_o  = (C_ * C_) / 4;         // 1048576
    int i = blockIdx.x * blockDim.x + threadIdx.x;
    const float* src; __half* dst;
    if (i < n_x)                         { src = sx; dst = dx; }
    else if (i < n_x + n_q)              { src = sq; dst = dq; i -= n_x; }
    else if (i < n_x + n_q + n_kv)       { src = sk; dst = dk; i -= n_x + n_q; }
    else if (i < n_x + n_q + 2 * n_kv)   { src = sv; dst = dv; i -= n_x + n_q + n_kv; }
    else if (i < n_x + n_q + 2 * n_kv + n_o) { src = sw; dst = dw; i -= n_x + n_q + 2 * n_kv; }
    else return;
    float4 v = ((const float4*)src)[i];
    __half2* d = (__half2*)dst + 2 * i;
    d[0] = __floats2half2_rn(v.x, v.y);
    d[1] = __floats2half2_rn(v.z, v.w);
}

// ---------------------------------------------------------------------------
// fp16 tensor-core sliding-window attention (window 256), GQA 16:4.
// Block = 4 warps / 64 queries; 3 blocks per SM.
// NEW: 64-key tiles, 2-stage double buffer, ONE barrier per tile (5 total
// vs 10). Inner 32-key compute body is the verified R12 code, run twice
// per tile with a 32-row smem offset. Q pre-scaled by log2(e)/sqrt(d).
// ---------------------------------------------------------------------------
#define AKST 136
#define AT_KB (64 * AKST * 2)            // 17408 (64-row K tile)
#define AT_STAGE (2 * AT_KB)             // 34816 (K + V)
#define AT_SMEM  (2 * AT_STAGE)          // 69632 -> 3 blocks = 209KB/SM

__global__ __launch_bounds__(128, 3) void attn_h(
    const __half* __restrict__ Qh, const __half* __restrict__ Kh,
    const __half* __restrict__ Vh, __half* __restrict__ Y)
{
    extern __shared__ __align__(128) char smem[];
    const uint32_t sb = smem_u32(smem);

    const int tid  = threadIdx.x;
    const int lane = tid & 31;
    const int w    = tid >> 5;          // 0..3
    const int g    = lane >> 2;
    const int tg   = lane & 3;
    const int b    = blockIdx.z;
    const int h    = blockIdx.y;
    const int c0   = blockIdx.x << 6;   // 64 queries per block
    const int kvh  = h >> 2;
    const int tr   = c0 + (w << 4) + g;

    const uint32_t qk_lbase = (lane & 7) * (AKST * 2) + ((lane >> 3) << 4);
    const uint32_t pv_lbase = ((((lane >> 3) & 1) << 3) + (lane & 7)) * (AKST * 2)
                              + ((lane >> 4) << 4);

    uint32_t qf[8][4];
    {
        const __half* q0 = Qh + ((size_t)(b * T_ + tr) * NH + h) * D_;
        const __half* q8 = q0 + (size_t)8 * NH * D_;
#pragma unroll
        for (int ks = 0; ks < 8; ks++) {
            const int c = ks * 16 + (tg << 1);
            qf[ks][0] = *(const uint32_t*)(q0 + c);
            qf[ks][1] = *(const uint32_t*)(q8 + c);
            qf[ks][2] = *(const uint32_t*)(q0 + c + 8);
            qf[ks][3] = *(const uint32_t*)(q8 + c + 8);
        }
    }

    float o[16][4];
#pragma unroll
    for (int i = 0; i < 16; i++)
#pragma unroll
        for (int e = 0; e < 4; e++) o[i][e] = 0.f;
    float l0 = 0.f, l1 = 0.f;

    // Load a 64-key tile (K + V), 16 cp16 per thread.
    auto load_tile = [&](int stage, int kbase) {
        const uint32_t kd = sb + stage * AT_STAGE;
        const uint32_t vd = kd + AT_KB;
#pragma unroll
        for (int i = 0; i < 8; i++) {
            int idx = tid + (i << 7);           // 0..1023
            int row = idx >> 4, seg = idx & 15; // row 0..63
            const size_t gofs =
                ((size_t)(b * T_ + kbase + row) * NKV + kvh) * D_ + (seg << 3);
            cp16(kd + row * (AKST * 2) + (seg << 4), Kh + gofs);
            cp16(vd + row * (AKST * 2) + (seg << 4), Vh + gofs);
        }
    };

    // Tiles tstart..4 cover keys [max(c0-256,0), c0+64)
    const int tstart = (c0 >= 256) ? 0 : ((256 - c0) >> 6);
    load_tile(tstart & 1, c0 - 256 + (tstart << 6));
    CP_COMMIT();

    const int wq0 = c0 + (w << 4);

    for (int t = tstart; t < 5; t++) {
        const int kbase = c0 - 256 + (t << 6);
        CP_WAIT0();              // tile t resident (single group in flight)
        __syncthreads();         // all warps done with the other stage
        if (t + 1 < 5) { load_tile((t + 1) & 1, kbase + 64); CP_COMMIT(); }

        const uint32_t Ksm0 = sb + (t & 1) * AT_STAGE;
        const uint32_t Vsm0 = Ksm0 + AT_KB;

#pragma unroll
        for (int hx = 0; hx < 2; hx++) {
            const int kb2 = kbase + (hx << 5);
            const int rel = kb2 - wq0;
            if (rel > 15 || rel < -287) continue;
            const uint32_t Ksm = Ksm0 + hx * (32 * AKST * 2);
            const uint32_t Vsm = Vsm0 + hx * (32 * AKST * 2);

            float sc[4][4];
#pragma unroll
            for (int nc = 0; nc < 4; nc++)
#pragma unroll
                for (int e = 0; e < 4; e++) sc[nc][e] = 0.f;

#pragma unroll
            for (int ksp = 0; ksp < 4; ksp++) {
#pragma unroll
                for (int nc = 0; nc < 4; nc++) {
                    uint32_t r0, r1, r2, r3;
                    const uint32_t addr = Ksm + nc * (8 * AKST * 2) + (ksp << 6) + qk_lbase;
                    ldsm_x4(r0, r1, r2, r3, addr);
                    uint32_t blo[2] = { r0, r1 };
                    uint32_t bhi[2] = { r2, r3 };
                    mma_f16(sc[nc], qf[2 * ksp],     blo);
                    mma_f16(sc[nc], qf[2 * ksp + 1], bhi);
                }
            }

            uint32_t pa[2][4];
            if (rel >= -240 && rel <= -32) {
                // fully-valid 32-key half: no masking (warp-uniform)
#pragma unroll
                for (int nc = 0; nc < 4; nc++) {
                    float p0 = ex2(sc[nc][0]);
                    float p1 = ex2(sc[nc][1]);
                    float p2 = ex2(sc[nc][2]);
                    float p3 = ex2(sc[nc][3]);
                    l0 += p0 + p1;
                    l1 += p2 + p3;
                    const int kc = nc >> 1;
                    const int hi = nc & 1;
                    pa[kc][2 * hi]     = h2u(__floats2half2_rn(p0, p1));
                    pa[kc][2 * hi + 1] = h2u(__floats2half2_rn(p2, p3));
                }
            } else {
#pragma unroll
                for (int nc = 0; nc < 4; nc++) {
                    const int col = kb2 + nc * 8 + (tg << 1);
                    float p0 = ((unsigned)(tr - col)     < 256u) ? ex2(sc[nc][0]) : 0.f;
                    float p1 = ((unsigned)(tr - col - 1) < 256u) ? ex2(sc[nc][1]) : 0.f;
                    float p2 = ((unsigned)(tr + 8 - col) < 256u) ? ex2(sc[nc][2]) : 0.f;
                    float p3 = ((unsigned)(tr + 7 - col) < 256u) ? ex2(sc[nc][3]) : 0.f;
                    l0 += p0 + p1;
                    l1 += p2 + p3;
                    const int kc = nc >> 1;
                    const int hi = nc & 1;
                    pa[kc][2 * hi]     = h2u(__floats2half2_rn(p0, p1));
                    pa[kc][2 * hi + 1] = h2u(__floats2half2_rn(p2, p3));
                }
            }

#pragma unroll
            for (int kc = 0; kc < 2; kc++) {
#pragma unroll
                for (int ncp = 0; ncp < 8; ncp++) {
                    uint32_t r0, r1, r2, r3;
                    const uint32_t addr = Vsm + kc * (16 * AKST * 2) + (ncp << 5) + pv_lbase;
                    ldsm_x4_t(r0, r1, r2, r3, addr);
                    uint32_t blo[2] = { r0, r1 };
                    uint32_t bhi[2] = { r2, r3 };
                    mma_f16(o[2 * ncp],     pa[kc], blo);
                    mma_f16(o[2 * ncp + 1], pa[kc], bhi);
                }
            }
        }
    }

    l0 += __shfl_xor_sync(0xffffffffu, l0, 1);
    l0 += __shfl_xor_sync(0xffffffffu, l0, 2);
    l1 += __shfl_xor_sync(0xffffffffu, l1, 1);
    l1 += __shfl_xor_sync(0xffffffffu, l1, 2);
    const float rl0 = 1.0f / l0;
    const float rl1 = 1.0f / l1;

    __half2* y0 = (__half2*)(Y + ((size_t)(b * T_ + tr) * NH + h) * D_);
    __half2* y8 = (__half2*)(Y + ((size_t)(b * T_ + tr + 8) * NH + h) * D_);
#pragma unroll
    for (int nc = 0; nc < 16; nc++) {
        const int dw = nc * 4 + tg;
        y0[dw] = __floats2half2_rn(o[nc][0] * rl0, o[nc][1] * rl0);
        y8[dw] = __floats2half2_rn(o[nc][2] * rl1, o[nc][3] * rl1);
    }
}

// ---------------------------------------------------------------------------
// Launch. Inputs (metadata order): x, wq, wk, wv, wo, rope_cache. Out: fp32.
// ---------------------------------------------------------------------------
extern "C" void kernel_launch(void* const* d_in, const int* in_sizes, int n_in,
                              void* d_out, int out_size)
{
    const float* x    = (const float*)d_in[0];
    const float* wq   = (const float*)d_in[1];
    const float* wk   = (const float*)d_in[2];
    const float* wv   = (const float*)d_in[3];
    const float* wo   = (const float*)d_in[4];
    const float* rope = (const float*)d_in[5];
    float* out = (float*)d_out;

    __half *pqh, *pkh, *pvh, *pyh, *pxh, *pwqh, *pwkh, *pwvh, *pwoh;
    cudaGetSymbolAddress((void**)&pqh,  g_qh);
    cudaGetSymbolAddress((void**)&pkh,  g_kh);
    cudaGetSymbolAddress((void**)&pvh,  g_vh);
    cudaGetSymbolAddress((void**)&pyh,  g_yh);
    cudaGetSymbolAddress((void**)&pxh,  g_xh);
    cudaGetSymbolAddress((void**)&pwqh, g_wqh);
    cudaGetSymbolAddress((void**)&pwkh, g_wkh);
    cudaGetSymbolAddress((void**)&pwvh, g_wvh);
    cudaGetSymbolAddress((void**)&pwoh, g_woh);

    cudaFuncSetAttribute(gemm_h<0>, cudaFuncAttributeMaxDynamicSharedMemorySize, GM_SMEM);
    cudaFuncSetAttribute(gemm_h<1>, cudaFuncAttributeMaxDynamicSharedMemorySize, GM_SMEM);
    cudaFuncSetAttribute(attn_h,    cudaFuncAttributeMaxDynamicSharedMemorySize, AT_SMEM);

    const int M = B_ * T_;  // 8192

    // One conversion launch for x + all weights
    {
        int n4 = (B_ * T_ * C_ + NH * D_ * C_ + 2 * NKV * D_ * C_ + C_ * C_) / 4;
        cvt_all<<<(n4 + 255) / 256, 256>>>(pxh, pwqh, pwkh, pwvh, pwoh,
                                           x, wq, wk, wv, wo);
    }

    // Fused QKV projection: 24 column-blocks (16 Q + 4 K + 4 V) x 64 row-blocks
    gemm_h<1><<<dim3(24, M / 128), 256, GM_SMEM>>>(
        pxh, pwqh, pwkh, pwvh, pqh, pkh, pvh, rope, M, C_);

    // fp16 tensor-core sliding-window attention -> yh (fp16)
    attn_h<<<dim3(T_ / 64, NH, B_), 128, AT_SMEM>>>(pqh, pkh, pvh, pyh);

    // Output projection (fp16 in, fp32 out)
    gemm_h<0><<<dim3(C_ / 128, M / 128), 256, GM_SMEM>>>(
        pyh, pwoh, nullptr, nullptr, out, nullptr, nullptr, nullptr, M, C_);
}

// round 17
// speedup vs baseline: 1.1148x; 1.0907x over previous
#include <cuda_runtime.h>
#include <cuda_fp16.h>
#include <cstdint>
#include <cstddef>

#define B_  2
#define T_  4096
#define C_  2048
#define NH  16
#define NKV 4
#define D_  128

// Scratch (allocation-free rule: __device__ globals)
__device__ __align__(256) __half g_qh[B_ * T_ * NH * D_];    // rope'd+scaled fp16 Q
__device__ __align__(256) __half g_kh[B_ * T_ * NKV * D_];   // rope'd fp16 K
__device__ __align__(256) __half g_vh[B_ * T_ * NKV * D_];   // fp16 V [B,T,KV,D]
__device__ __align__(256) __half g_yh[B_ * T_ * NH * D_];    // fp16 attention out
__device__ __align__(256) __half g_xh [B_ * T_ * C_];        // fp16 GEMM inputs
__device__ __align__(256) __half g_wqh[NH * D_ * C_];
__device__ __align__(256) __half g_wkh[NKV * D_ * C_];
__device__ __align__(256) __half g_wvh[NKV * D_ * C_];
__device__ __align__(256) __half g_woh[C_ * C_];

// ---------------------------------------------------------------------------
// Helpers (arch-agnostic PTX only — GPU-side build targets plain sm_103,
// which rejects all sm_103a-only features like tcgen05)
// ---------------------------------------------------------------------------
__device__ __forceinline__ uint32_t smem_u32(const void* p) {
    uint32_t a;
    asm("{ .reg .u64 t; cvta.to.shared.u64 t, %1; cvt.u32.u64 %0, t; }"
        : "=r"(a) : "l"(p));
    return a;
}

__device__ __forceinline__ void cp16(uint32_t dst, const void* src) {
    asm volatile("cp.async.cg.shared.global [%0], [%1], 16;\n"
                 :: "r"(dst), "l"(src));
}
#define CP_COMMIT() asm volatile("cp.async.commit_group;" ::: "memory")
#define CP_WAIT0()  asm volatile("cp.async.wait_group 0;" ::: "memory")

// mbarrier primitives (sm_80/90 PTX, legal on plain sm_103 target)
#define MBI(addr, cnt) \
    asm volatile("mbarrier.init.shared.b64 [%0], %1;" :: "r"(addr), "r"(cnt) : "memory")
#define MB_WAIT(addr, ph) do {                                          \
    asm volatile("{\n\t.reg .pred P1;\n\t"                              \
        "W_%=:\n\t"                                                     \
        "mbarrier.try_wait.parity.shared.b64 P1, [%0], %1;\n\t"         \
        "@P1 bra.uni D_%=;\n\t"                                         \
        "bra.uni W_%=;\n\t"                                             \
        "D_%=:\n\t}" :: "r"(addr), "r"(ph) : "memory");                 \
} while (0)
#define CP_MB_ARRIVE(addr) \
    asm volatile("cp.async.mbarrier.arrive.noinc.shared.b64 [%0];" :: "r"(addr) : "memory")
#define MB_ARRIVE(addr) do { uint64_t _t;                               \
    asm volatile("mbarrier.arrive.shared.b64 %0, [%1];"                 \
                 : "=l"(_t) : "r"(addr) : "memory"); } while (0)

// fp16 mma, fp32 accumulate: D[16x8] += A[16x16] * B[16x8]
__device__ __forceinline__ void mma_f16(float* c, const uint32_t* a, const uint32_t* b) {
    asm volatile(
        "mma.sync.aligned.m16n8k16.row.col.f32.f16.f16.f32 "
        "{%0,%1,%2,%3}, {%4,%5,%6,%7}, {%8,%9}, {%0,%1,%2,%3};\n"
        : "+f"(c[0]), "+f"(c[1]), "+f"(c[2]), "+f"(c[3])
        : "r"(a[0]), "r"(a[1]), "r"(a[2]), "r"(a[3]),
          "r"(b[0]), "r"(b[1]));
}

__device__ __forceinline__ void ldsm_x4(uint32_t& r0, uint32_t& r1,
                                        uint32_t& r2, uint32_t& r3, uint32_t addr) {
    asm volatile("ldmatrix.sync.aligned.m8n8.x4.shared.b16 {%0,%1,%2,%3}, [%4];"
                 : "=r"(r0), "=r"(r1), "=r"(r2), "=r"(r3) : "r"(addr));
}

__device__ __forceinline__ void ldsm_x4_t(uint32_t& r0, uint32_t& r1,
                                          uint32_t& r2, uint32_t& r3, uint32_t addr) {
    asm volatile("ldmatrix.sync.aligned.m8n8.x4.trans.shared.b16 {%0,%1,%2,%3}, [%4];"
                 : "=r"(r0), "=r"(r1), "=r"(r2), "=r"(r3) : "r"(addr));
}

__device__ __forceinline__ uint32_t h2u(__half2 h) {
    return *reinterpret_cast<uint32_t*>(&h);
}

__device__ __forceinline__ float ex2(float x) {
    float r;
    asm("ex2.approx.f32 %0, %1;" : "=f"(r) : "f"(x));
    return r;
}

// ---------------------------------------------------------------------------
// fp16 GEMM — occupancy-2, warp 64x32, 3-stage pipeline. NEW: block-wide
// __syncthreads replaced by per-stage full/empty mbarriers so warps slip
// instead of lockstepping every k-tile (convoy was the measured bottleneck:
// R9 2-barrier 46% tensor -> R12 1-barrier 60%).
//   full[s]:  count 256, armed per-thread by cp.async.mbarrier.arrive.noinc
//   empty[s]: count 8, one mbarrier.arrive per warp after its ldsm reads
// FUSED=1: QKV fused — bx in [0,24): 16 Q (+rope, +exp2 prescale), 4 K
//          (+rope), 4 V. FUSED=0: out-projection, fp32 destination.
// ---------------------------------------------------------------------------
#define HST 72
#define TST_B   (128 * HST * 2)           // 18432 (one A or B tile)
#define STAGE_B (2 * TST_B)               // 36864 (A+B per stage)
#define GM_SMEM (3 * STAGE_B + 64)        // 110656 -> 2 blocks = 221KB/SM

template <int FUSED>
__global__ __launch_bounds__(256, 2) void gemm_h(
    const __half* __restrict__ A,
    const __half* __restrict__ B0, const __half* __restrict__ B1,
    const __half* __restrict__ B2,
    void* __restrict__ D0, void* __restrict__ D1, void* __restrict__ D2,
    const float* __restrict__ rope, int M, int K)
{
    extern __shared__ __align__(128) char smem[];
    const uint32_t sbase = smem_u32(smem);
    const uint32_t fb = sbase + 3 * STAGE_B;   // full[s]  = fb + 8s
    const uint32_t eb = fb + 24;               // empty[s] = eb + 8s

    const int tid  = threadIdx.x;
    const int lane = tid & 31;
    const int warp = tid >> 5;
    const int g    = lane >> 2;
    const int tg   = lane & 3;
    const int wm   = warp & 1;
    const int wn   = warp >> 1;
    const int bm   = blockIdx.y << 7;
    const int bx   = blockIdx.x;

    if (tid == 0) {
#pragma unroll
        for (int s = 0; s < 3; s++) {
            MBI(fb + s * 8, 256);
            MBI(eb + s * 8, 8);
        }
    }
    __syncthreads();   // one-time: barrier inits visible before any arrive

    // Per-block output selection (uniform across the block)
    const __half* Bg;
    char* Dst;
    int   Nout, coln0;
    bool  dorope;
    float osc = 1.0f;                     // epilogue output scale (Q only)
    if (FUSED) {
        if (bx < 16)      { coln0 = bx << 7;        Bg = B0 + (size_t)coln0 * K; Dst = (char*)D0; Nout = 2048; dorope = true;
                            osc = 0.1275174325f; }  // log2(e)/sqrt(128)
        else if (bx < 20) { coln0 = (bx - 16) << 7; Bg = B1 + (size_t)coln0 * K; Dst = (char*)D1; Nout = 512;  dorope = true;  }
        else              { coln0 = (bx - 20) << 7; Bg = B2 + (size_t)coln0 * K; Dst = (char*)D2; Nout = 512;  dorope = false; }
    } else {
        coln0 = bx << 7;
        Bg = B0 + (size_t)coln0 * K;
        Dst = (char*)D0; Nout = 2048; dorope = false;
    }

    const int arow = tid >> 3;          // 0..31
    const int aseg = tid & 7;           // 16B segs (8 per 128B row)

    // ldmatrix lane offsets (byte units)
    const uint32_t a_lrow = (lane & 7) + (((lane >> 3) & 1) << 3);
    const uint32_t a_kofb = (lane >> 4) << 4;
    const uint32_t b_lrow = (lane & 7) + ((lane >> 4) << 3);
    const uint32_t b_kofb = ((lane >> 3) & 1) << 4;

    float acc[4][4][4];
#pragma unroll
    for (int i = 0; i < 4; i++)
#pragma unroll
        for (int j = 0; j < 4; j++)
#pragma unroll
            for (int e = 0; e < 4; e++) acc[i][j][e] = 0.f;

    const __half* Ag = A + (size_t)bm * K;

    auto load_stage = [&](int sp, int kt) {
        const __half* As = Ag + (kt << 6);
        const __half* Bs = Bg + (kt << 6);
        const uint32_t ab = sbase + sp * STAGE_B;
        const uint32_t bb = ab + TST_B;
#pragma unroll
        for (int i = 0; i < 4; i++) {
            int row = arow + (i << 5);
            cp16(ab + row * (HST * 2) + (aseg << 4), As + (size_t)row * K + (aseg << 3));
        }
#pragma unroll
        for (int i = 0; i < 4; i++) {
            int row = arow + (i << 5);
            cp16(bb + row * (HST * 2) + (aseg << 4), Bs + (size_t)row * K + (aseg << 3));
        }
    };

    const int nkt = K >> 6;   // 32 for K=2048

    // producer cursor (stage, parity) — parity starts 1 so first empty-wait
    // on a fresh barrier passes immediately; flips on ring wrap.
    int ps = 0, pph = 1;
    // consumer cursor
    int cs = 0, cph = 0;

    // prologue: tiles 0,1 into stages 0,1
#pragma unroll
    for (int t = 0; t < 2; t++) {
        MB_WAIT(eb + ps * 8, pph);
        load_stage(ps, t);
        CP_MB_ARRIVE(fb + ps * 8);
        if (++ps == 3) { ps = 0; pph ^= 1; }
    }

    for (int kt = 0; kt < nkt; kt++) {
        if (kt + 2 < nkt) {
            MB_WAIT(eb + ps * 8, pph);          // prior readers of stage done
            load_stage(ps, kt + 2);
            CP_MB_ARRIVE(fb + ps * 8);
            if (++ps == 3) { ps = 0; pph ^= 1; }
        }

        MB_WAIT(fb + cs * 8, cph);              // tile kt data resident
        const uint32_t Asm = sbase + cs * STAGE_B;
        const uint32_t Bsm = Asm + TST_B;

#pragma unroll
        for (int ks = 0; ks < 4; ks++) {
            uint32_t af[4][4];
            uint32_t bf[4][2];
#pragma unroll
            for (int mt = 0; mt < 4; mt++) {
                const uint32_t addr = Asm +
                    ((wm << 6) + (mt << 4) + a_lrow) * (HST * 2) + (ks << 5) + a_kofb;
                ldsm_x4(af[mt][0], af[mt][1], af[mt][2], af[mt][3], addr);
            }
#pragma unroll
            for (int ntp = 0; ntp < 2; ntp++) {
                const uint32_t addr = Bsm +
                    ((wn << 5) + (ntp << 4) + b_lrow) * (HST * 2) + (ks << 5) + b_kofb;
                ldsm_x4(bf[2 * ntp][0], bf[2 * ntp][1],
                        bf[2 * ntp + 1][0], bf[2 * ntp + 1][1], addr);
            }
#pragma unroll
            for (int mt = 0; mt < 4; mt++)
#pragma unroll
                for (int nt = 0; nt < 4; nt++)
                    mma_f16(acc[mt][nt], af[mt], bf[nt]);
        }

        if (lane == 0) MB_ARRIVE(eb + cs * 8);  // warp done reading stage cs
        if (++cs == 3) { cs = 0; cph ^= 1; }
    }

#pragma unroll
    for (int mt = 0; mt < 4; mt++) {
#pragma unroll
        for (int nt = 0; nt < 4; nt++) {
            float v0 = acc[mt][nt][0], v1 = acc[mt][nt][1];
            float v2 = acc[mt][nt][2], v3 = acc[mt][nt][3];
            const int row = bm + (wm << 6) + (mt << 4) + g;
            const int col = coln0 + (wn << 5) + (nt << 3) + (tg << 1);
            if (FUSED && dorope) {
                const int t = row & (T_ - 1);
                const int d = col & 127;
                float2 cs0 = *(const float2*)(rope + (size_t)t * 128 + d);
                float2 cs8 = *(const float2*)(rope + (size_t)(t + 8) * 128 + d);
                float o0 = (v0 * cs0.x - v1 * cs0.y) * osc;
                float o1 = (v0 * cs0.y + v1 * cs0.x) * osc;
                float o2 = (v2 * cs8.x - v3 * cs8.y) * osc;
                float o3 = (v2 * cs8.y + v3 * cs8.x) * osc;
                v0 = o0; v1 = o1; v2 = o2; v3 = o3;
            }
            if (FUSED) {
                __half* C = (__half*)Dst;
                *(__half2*)(C + (size_t)row * Nout + col) = __floats2half2_rn(v0, v1);
                *(__half2*)(C + (size_t)(row + 8) * Nout + col) = __floats2half2_rn(v2, v3);
            } else {
                float* C = (float*)Dst;
                *(float2*)(C + (size_t)row * Nout + col) = make_float2(v0, v1);
                *(float2*)(C + (size_t)(row + 8) * Nout + col) = make_float2(v2, v3);
            }
        }
    }
}

// ---------------------------------------------------------------------------
// All fp32->fp16 conversions (x + 4 weight matrices) in ONE launch.
// ---------------------------------------------------------------------------
__global__ void cvt_all(__half* dx, __half* dq, __half* dk, __half* dv, __half* dw,
                        const float* sx, const float* sq, const float* sk,
                        const float* sv, const float* sw)
{
    const int n_x  = (B_ * T_ * C_) / 4;    // 4194304
    const int n_q  = (NH  * D_ * C_) / 4;   // 1048576
    const int n_kv = (NKV * D_ * C_) / 4;   // 262144
    const int n_o  = (C_ * C_) / 4;         // 1048576
    int i = blockIdx.x * blockDim.x + threadIdx.x;
    const float* src; __half* dst;
    if (i < n_x)                         { src = sx; dst = dx; }
    else if (i < n_x + n_q)              { src = sq; dst = dq; i -= n_x; }
    else if (i < n_x + n_q + n_kv)       { src = sk; dst = dk; i -= n_x + n_q; }
    else if (i < n_x + n_q + 2 * n_kv)   { src = sv; dst = dv; i -= n_x + n_q + n_kv; }
    else if (i < n_x + n_q + 2 * n_kv + n_o) { src = sw; dst = dw; i -= n_x + n_q + 2 * n_kv; }
    else return;
    float4 v = ((const float4*)src)[i];
    __half2* d = (__half2*)dst + 2 * i;
    d[0] = __floats2half2_rn(v.x, v.y);
    d[1] = __floats2half2_rn(v.z, v.w);
}

// ---------------------------------------------------------------------------
// fp16 tensor-core sliding-window attention (window 256), GQA 16:4.
// Block = 4 warps / 64 queries; 3 blocks per SM. 64-key tiles, 2-stage
// double buffer, one barrier per tile (R16, proven). Q pre-scaled by
// log2(e)/sqrt(d) -> p = ex2(s). Warp-uniform fast path for valid halves.
// ---------------------------------------------------------------------------
#define AKST 136
#define AT_KB (64 * AKST * 2)            // 17408 (64-row K tile)
#define AT_STAGE (2 * AT_KB)             // 34816 (K + V)
#define AT_SMEM  (2 * AT_STAGE)          // 69632 -> 3 blocks = 209KB/SM

__global__ __launch_bounds__(128, 3) void attn_h(
    const __half* __restrict__ Qh, const __half* __restrict__ Kh,
    const __half* __restrict__ Vh, __half* __restrict__ Y)
{
    extern __shared__ __align__(128) char smem[];
    const uint32_t sb = smem_u32(smem);

    const int tid  = threadIdx.x;
    const int lane = tid & 31;
    const int w    = tid >> 5;          // 0..3
    const int g    = lane >> 2;
    const int tg   = lane & 3;
    const int b    = blockIdx.z;
    const int h    = blockIdx.y;
    const int c0   = blockIdx.x << 6;   // 64 queries per block
    const int kvh  = h >> 2;
    const int tr   = c0 + (w << 4) + g;

    const uint32_t qk_lbase = (lane & 7) * (AKST * 2) + ((lane >> 3) << 4);
    const uint32_t pv_lbase = ((((lane >> 3) & 1) << 3) + (lane & 7)) * (AKST * 2)
                              + ((lane >> 4) << 4);

    uint32_t qf[8][4];
    {
        const __half* q0 = Qh + ((size_t)(b * T_ + tr) * NH + h) * D_;
        const __half* q8 = q0 + (size_t)8 * NH * D_;
#pragma unroll
        for (int ks = 0; ks < 8; ks++) {
            const int c = ks * 16 + (tg << 1);
            qf[ks][0] = *(const uint32_t*)(q0 + c);
            qf[ks][1] = *(const uint32_t*)(q8 + c);
            qf[ks][2] = *(const uint32_t*)(q0 + c + 8);
            qf[ks][3] = *(const uint32_t*)(q8 + c + 8);
        }
    }

    float o[16][4];
#pragma unroll
    for (int i = 0; i < 16; i++)
#pragma unroll
        for (int e = 0; e < 4; e++) o[i][e] = 0.f;
    float l0 = 0.f, l1 = 0.f;

    // Load a 64-key tile (K + V), 16 cp16 per thread.
    auto load_tile = [&](int stage, int kbase) {
        const uint32_t kd = sb + stage * AT_STAGE;
        const uint32_t vd = kd + AT_KB;
#pragma unroll
        for (int i = 0; i < 8; i++) {
            int idx = tid + (i << 7);           // 0..1023
            int row = idx >> 4, seg = idx & 15; // row 0..63
            const size_t gofs =
                ((size_t)(b * T_ + kbase + row) * NKV + kvh) * D_ + (seg << 3);
            cp16(kd + row * (AKST * 2) + (seg << 4), Kh + gofs);
            cp16(vd + row * (AKST * 2) + (seg << 4), Vh + gofs);
        }
    };

    // Tiles tstart..4 cover keys [max(c0-256,0), c0+64)
    const int tstart = (c0 >= 256) ? 0 : ((256 - c0) >> 6);
    load_tile(tstart & 1, c0 - 256 + (tstart << 6));
    CP_COMMIT();

    const int wq0 = c0 + (w << 4);

    for (int t = tstart; t < 5; t++) {
        const int kbase = c0 - 256 + (t << 6);
        CP_WAIT0();              // tile t resident (single group in flight)
        __syncthreads();         // all warps done with the other stage
        if (t + 1 < 5) { load_tile((t + 1) & 1, kbase + 64); CP_COMMIT(); }

        const uint32_t Ksm0 = sb + (t & 1) * AT_STAGE;
        const uint32_t Vsm0 = Ksm0 + AT_KB;

#pragma unroll
        for (int hx = 0; hx < 2; hx++) {
            const int kb2 = kbase + (hx << 5);
            const int rel = kb2 - wq0;
            if (rel > 15 || rel < -287) continue;
            const uint32_t Ksm = Ksm0 + hx * (32 * AKST * 2);
            const uint32_t Vsm = Vsm0 + hx * (32 * AKST * 2);

            float sc[4][4];
#pragma unroll
            for (int nc = 0; nc < 4; nc++)
#pragma unroll
                for (int e = 0; e < 4; e++) sc[nc][e] = 0.f;

#pragma unroll
            for (int ksp = 0; ksp < 4; ksp++) {
#pragma unroll
                for (int nc = 0; nc < 4; nc++) {
                    uint32_t r0, r1, r2, r3;
                    const uint32_t addr = Ksm + nc * (8 * AKST * 2) + (ksp << 6) + qk_lbase;
                    ldsm_x4(r0, r1, r2, r3, addr);
                    uint32_t blo[2] = { r0, r1 };
                    uint32_t bhi[2] = { r2, r3 };
                    mma_f16(sc[nc], qf[2 * ksp],     blo);
                    mma_f16(sc[nc], qf[2 * ksp + 1], bhi);
                }
            }

            uint32_t pa[2][4];
            if (rel >= -240 && rel <= -32) {
                // fully-valid 32-key half: no masking (warp-uniform)
#pragma unroll
                for (int nc = 0; nc < 4; nc++) {
                    float p0 = ex2(sc[nc][0]);
                    float p1 = ex2(sc[nc][1]);
                    float p2 = ex2(sc[nc][2]);
                    float p3 = ex2(sc[nc][3]);
                    l0 += p0 + p1;
                    l1 += p2 + p3;
                    const int kc = nc >> 1;
                    const int hi = nc & 1;
                    pa[kc][2 * hi]     = h2u(__floats2half2_rn(p0, p1));
                    pa[kc][2 * hi + 1] = h2u(__floats2half2_rn(p2, p3));
                }
            } else {
#pragma unroll
                for (int nc = 0; nc < 4; nc++) {
                    const int col = kb2 + nc * 8 + (tg << 1);
                    float p0 = ((unsigned)(tr - col)     < 256u) ? ex2(sc[nc][0]) : 0.f;
                    float p1 = ((unsigned)(tr - col - 1) < 256u) ? ex2(sc[nc][1]) : 0.f;
                    float p2 = ((unsigned)(tr + 8 - col) < 256u) ? ex2(sc[nc][2]) : 0.f;
                    float p3 = ((unsigned)(tr + 7 - col) < 256u) ? ex2(sc[nc][3]) : 0.f;
                    l0 += p0 + p1;
                    l1 += p2 + p3;
                    const int kc = nc >> 1;
                    const int hi = nc & 1;
                    pa[kc][2 * hi]     = h2u(__floats2half2_rn(p0, p1));
                    pa[kc][2 * hi + 1] = h2u(__floats2half2_rn(p2, p3));
                }
            }

#pragma unroll
            for (int kc = 0; kc < 2; kc++) {
#pragma unroll
                for (int ncp = 0; ncp < 8; ncp++) {
                    uint32_t r0, r1, r2, r3;
                    const uint32_t addr = Vsm + kc * (16 * AKST * 2) + (ncp << 5) + pv_lbase;
                    ldsm_x4_t(r0, r1, r2, r3, addr);
                    uint32_t blo[2] = { r0, r1 };
                    uint32_t bhi[2] = { r2, r3 };
                    mma_f16(o[2 * ncp],     pa[kc], blo);
                    mma_f16(o[2 * ncp + 1], pa[kc], bhi);
                }
            }
        }
    }

    l0 += __shfl_xor_sync(0xffffffffu, l0, 1);
    l0 += __shfl_xor_sync(0xffffffffu, l0, 2);
    l1 += __shfl_xor_sync(0xffffffffu, l1, 1);
    l1 += __shfl_xor_sync(0xffffffffu, l1, 2);
    const float rl0 = 1.0f / l0;
    const float rl1 = 1.0f / l1;

    __half2* y0 = (__half2*)(Y + ((size_t)(b * T_ + tr) * NH + h) * D_);
    __half2* y8 = (__half2*)(Y + ((size_t)(b * T_ + tr + 8) * NH + h) * D_);
#pragma unroll
    for (int nc = 0; nc < 16; nc++) {
        const int dw = nc * 4 + tg;
        y0[dw] = __floats2half2_rn(o[nc][0] * rl0, o[nc][1] * rl0);
        y8[dw] = __floats2half2_rn(o[nc][2] * rl1, o[nc][3] * rl1);
    }
}

// ---------------------------------------------------------------------------
// Launch. Inputs (metadata order): x, wq, wk, wv, wo, rope_cache. Out: fp32.
// ---------------------------------------------------------------------------
extern "C" void kernel_launch(void* const* d_in, const int* in_sizes, int n_in,
                              void* d_out, int out_size)
{
    const float* x    = (const float*)d_in[0];
    const float* wq   = (const float*)d_in[1];
    const float* wk   = (const float*)d_in[2];
    const float* wv   = (const float*)d_in[3];
    const float* wo   = (const float*)d_in[4];
    const float* rope = (const float*)d_in[5];
    float* out = (float*)d_out;

    __half *pqh, *pkh, *pvh, *pyh, *pxh, *pwqh, *pwkh, *pwvh, *pwoh;
    cudaGetSymbolAddress((void**)&pqh,  g_qh);
    cudaGetSymbolAddress((void**)&pkh,  g_kh);
    cudaGetSymbolAddress((void**)&pvh,  g_vh);
    cudaGetSymbolAddress((void**)&pyh,  g_yh);
    cudaGetSymbolAddress((void**)&pxh,  g_xh);
    cudaGetSymbolAddress((void**)&pwqh, g_wqh);
    cudaGetSymbolAddress((void**)&pwkh, g_wkh);
    cudaGetSymbolAddress((void**)&pwvh, g_wvh);
    cudaGetSymbolAddress((void**)&pwoh, g_woh);

    cudaFuncSetAttribute(gemm_h<0>, cudaFuncAttributeMaxDynamicSharedMemorySize, GM_SMEM);
    cudaFuncSetAttribute(gemm_h<1>, cudaFuncAttributeMaxDynamicSharedMemorySize, GM_SMEM);
    cudaFuncSetAttribute(attn_h,    cudaFuncAttributeMaxDynamicSharedMemorySize, AT_SMEM);

    const int M = B_ * T_;  // 8192

    // One conversion launch for x + all weights
    {
        int n4 = (B_ * T_ * C_ + NH * D_ * C_ + 2 * NKV * D_ * C_ + C_ * C_) / 4;
        cvt_all<<<(n4 + 255) / 256, 256>>>(pxh, pwqh, pwkh, pwvh, pwoh,
                                           x, wq, wk, wv, wo);
    }

    // Fused QKV projection: 24 column-blocks (16 Q + 4 K + 4 V) x 64 row-blocks
    gemm_h<1><<<dim3(24, M / 128), 256, GM_SMEM>>>(
        pxh, pwqh, pwkh, pwvh, pqh, pkh, pvh, rope, M, C_);

    // fp16 tensor-core sliding-window attention -> yh (fp16)
    attn_h<<<dim3(T_ / 64, NH, B_), 128, AT_SMEM>>>(pqh, pkh, pvh, pyh);

    // Output projection (fp16 in, fp32 out)
    gemm_h<0><<<dim3(C_ / 128, M / 128), 256, GM_SMEM>>>(
        pyh, pwoh, nullptr, nullptr, out, nullptr, nullptr, nullptr, M, C_);
}